// round 16
// baseline (speedup 1.0000x reference)
#include <cuda_runtime.h>
#include <cuda_bf16.h>
#include <math.h>
#include <stdint.h>

#define BB   64
#define TT   1024
#define HH   512
#define G4   2048        // 4*H
#define MTOT (BB * TT)   // 65536

// ---- static device scratch (no allocation allowed) ----
__device__ float g_xg[(size_t)MTOT * G4];     // 512 MB: per-layer input projection
__device__ uint32_t g_hpack[2][BB * HH];      // ping-pong h as packed (bf16 hi | lo<<16)
__device__ __align__(128) unsigned g_flag[4][32]; // per-(group,slot) publication stamps

// bf16 split operands for the tensor-core input projection
__device__ __nv_bfloat16 g_xh[(size_t)MTOT * HH];  // 64 MB
__device__ __nv_bfloat16 g_xl[(size_t)MTOT * HH];  // 64 MB
__device__ __nv_bfloat16 g_wh[(size_t)G4 * HH];    // 2 MB
__device__ __nv_bfloat16 g_wl[(size_t)G4 * HH];    // 2 MB

// ============================================================
// small PTX helpers (all base-sm_103-safe)
// ============================================================
__device__ __forceinline__ uint32_t smem_u32(const void* p) {
    uint32_t a;
    asm("{ .reg .u64 t; cvta.to.shared.u64 t, %1; cvt.u32.u64 %0, t; }"
        : "=r"(a) : "l"(p));
    return a;
}
__device__ __forceinline__ void ldsm4(uint32_t* r, uint32_t addr) {
    asm volatile("ldmatrix.sync.aligned.m8n8.x4.shared.b16 {%0,%1,%2,%3}, [%4];"
        : "=r"(r[0]), "=r"(r[1]), "=r"(r[2]), "=r"(r[3]) : "r"(addr));
}
__device__ __forceinline__ void mma_bf16(float* d, const uint32_t* a, const uint32_t* b) {
    asm volatile(
        "mma.sync.aligned.m16n8k16.row.col.f32.bf16.bf16.f32 "
        "{%0,%1,%2,%3}, {%4,%5,%6,%7}, {%8,%9}, {%0,%1,%2,%3};"
        : "+f"(d[0]), "+f"(d[1]), "+f"(d[2]), "+f"(d[3])
        : "r"(a[0]), "r"(a[1]), "r"(a[2]), "r"(a[3]), "r"(b[0]), "r"(b[1]));
}
__device__ __forceinline__ void cpa16(uint32_t smaddr, const void* g) {
    asm volatile("cp.async.cg.shared.global [%0], [%1], 16;" :: "r"(smaddr), "l"(g));
}
#define CPA_COMMIT() asm volatile("cp.async.commit_group;" ::: "memory")
#define CPA_WAIT0()  asm volatile("cp.async.wait_group 0;" ::: "memory")

// L2-only vector load (never L1-stale for cross-SM data)
__device__ __forceinline__ uint4 ldcg4(const void* p) {
    uint4 v;
    asm volatile("ld.global.cg.v4.u32 {%0,%1,%2,%3}, [%4];"
        : "=r"(v.x), "=r"(v.y), "=r"(v.z), "=r"(v.w) : "l"(p));
    return v;
}

// ============================================================
// fp32 -> bf16 hi/lo split
// ============================================================
__global__ __launch_bounds__(256) void split_bf16(const float* __restrict__ in,
                                                  __nv_bfloat16* __restrict__ hi,
                                                  __nv_bfloat16* __restrict__ lo)
{
    int i = blockIdx.x * 256 + threadIdx.x;
    float v = in[i];
    __nv_bfloat16 h = __float2bfloat16_rn(v);
    hi[i] = h;
    lo[i] = __float2bfloat16_rn(v - __bfloat162float(h));
}

// ============================================================
// Input projection via mma.sync bf16 (3-pass hi/lo split)  [unchanged]
// ============================================================
#define AP       40
#define ARR_BF16 (128 * AP)
#define XG2_BIAS (8 * ARR_BF16 * 2)
#define XG2_SMEM (XG2_BIAS + 512 + 16)

__global__ __launch_bounds__(256) void xg_mma2(const float* __restrict__ bih,
                                               const float* __restrict__ bhh)
{
    extern __shared__ __align__(16) char sm2[];
    float* bias_sm = (float*)(sm2 + XG2_BIAS);
    const uint32_t smb = smem_u32(sm2);

    const int tid  = threadIdx.x;
    const int wid  = tid >> 5;
    const int lane = tid & 31;
    const int n_blk = blockIdx.x * 128;
    const int m_blk = blockIdx.y * 128;
    const int wm = wid & 1;
    const int wn = wid >> 1;

    if (tid < 128)
        bias_sm[tid] = __ldg(bih + n_blk + tid) + __ldg(bhh + n_blk + tid);

    const __nv_bfloat16* src[4] = {
        g_xh + (size_t)m_blk * HH, g_xl + (size_t)m_blk * HH,
        g_wh + (size_t)n_blk * HH, g_wl + (size_t)n_blk * HH };

    auto load_chunk = [&](int buf, int kc) {
#pragma unroll
        for (int a = 0; a < 4; a++) {
#pragma unroll
            for (int r = 0; r < 2; r++) {
                int unit = tid + r * 256;
                int row  = unit >> 2;
                int u    = unit & 3;
                uint32_t dst = smb +
                    (uint32_t)(((buf * 4 + a) * ARR_BF16 + row * AP + u * 8) * 2);
                cpa16(dst, src[a] + (size_t)row * HH + kc * 32 + u * 8);
            }
        }
    };

    float acc[4][4][4];
#pragma unroll
    for (int i = 0; i < 4; i++)
#pragma unroll
        for (int j = 0; j < 4; j++)
#pragma unroll
            for (int q = 0; q < 4; q++) acc[i][j][q] = 0.f;

    load_chunk(0, 0);
    CPA_COMMIT();

    const int arow  = lane & 15;
    const int asel  = (lane >> 4) << 3;
    const int brow  = (lane & 7) + ((lane >> 4) << 3);
    const int bsel  = ((lane >> 3) & 1) << 3;

    for (int c = 0; c < 16; c++) {
        CPA_WAIT0();
        __syncthreads();
        if (c < 15) { load_chunk((c + 1) & 1, c + 1); CPA_COMMIT(); }

        const uint32_t bufb = smb + (uint32_t)((c & 1) * 4 * ARR_BF16 * 2);
        const uint32_t ah = bufb;
        const uint32_t al = bufb + ARR_BF16 * 2;
        const uint32_t bh = bufb + 2 * ARR_BF16 * 2;
        const uint32_t bl = bufb + 3 * ARR_BF16 * 2;

#pragma unroll
        for (int k16 = 0; k16 < 2; k16++) {
            const int ka = k16 * 16 + asel;
            const int kb = k16 * 16 + bsel;
            uint32_t fah[4][4], fal[4][4], fbh[2][4], fbl[2][4];
#pragma unroll
            for (int ma = 0; ma < 4; ma++) {
                uint32_t off = (uint32_t)(((wm * 64 + ma * 16 + arow) * AP + ka) * 2);
                ldsm4(fah[ma], ah + off);
                ldsm4(fal[ma], al + off);
            }
#pragma unroll
            for (int nb = 0; nb < 2; nb++) {
                uint32_t off = (uint32_t)(((wn * 32 + nb * 16 + brow) * AP + kb) * 2);
                ldsm4(fbh[nb], bh + off);
                ldsm4(fbl[nb], bl + off);
            }
#pragma unroll
            for (int ma = 0; ma < 4; ma++) {
#pragma unroll
                for (int n = 0; n < 4; n++) {
                    const uint32_t* bhf = &fbh[n >> 1][(n & 1) * 2];
                    const uint32_t* blf = &fbl[n >> 1][(n & 1) * 2];
                    mma_bf16(acc[ma][n], fah[ma], bhf);
                    mma_bf16(acc[ma][n], fah[ma], blf);
                    mma_bf16(acc[ma][n], fal[ma], bhf);
                }
            }
        }
    }
    __syncthreads();

    const int r = lane >> 2;
    const int q = lane & 3;
#pragma unroll
    for (int ma = 0; ma < 4; ma++) {
#pragma unroll
        for (int n = 0; n < 4; n++) {
            int m   = m_blk + wm * 64 + ma * 16 + r;
            int col = wn * 32 + n * 8 + q * 2;
            float b0 = bias_sm[col], b1 = bias_sm[col + 1];
            float2 v0, v1;
            v0.x = acc[ma][n][0] + b0; v0.y = acc[ma][n][1] + b1;
            v1.x = acc[ma][n][2] + b0; v1.y = acc[ma][n][3] + b1;
            *(float2*)(g_xg + (size_t)m * G4 + n_blk + col)       = v0;
            *(float2*)(g_xg + (size_t)(m + 8) * G4 + n_blk + col) = v1;
        }
    }
}

// ============================================================
// Persistent recurrence kernel — R15 base + barrier de-blocking:
//  * release broadcast via smem go-flag (warp 0 polls g_flag — protected
//    invariant — then stores s_go; warps 1-15 spin on LDS broadcast).
//  * pw barrier: gate warps (0-7) bar.sync 6,512; non-gate warps (8-15)
//    bar.arrive 6,512 (non-blocking) and run ahead into step t+1
//    (their hh_s/hl_s columns and pw rows are disjoint; pw(t+1) stores
//    are ordered behind the gates' pw(t) reads via the flag chain).
// Everything else identical to R15 (13.78ms).
// ============================================================
#define NCTA 128
#define HP   520                         // bf16 pitch

// steady-state smem (aliases the init-only W staging region)
#define HH_OFF   0                       // 16*520*2 = 16640
#define HL_OFF   16640                   // 16640
#define PW_OFF   33280                   // 4*16*68*4 = 17408
#define GA_OFF   50688                   // 16*68*4  = 4352
// init-only W staging
#define WH_OFF   0                       // 64*520*2 = 66560
#define WL_OFF   66560
#define REC_SMEM 133120

__global__ __launch_bounds__(512, 1) void rec_persist(const float* __restrict__ Whh,
                                                      float* __restrict__ outf,
                                                      __nv_bfloat16* __restrict__ outh,
                                                      __nv_bfloat16* __restrict__ outl,
                                                      int final_layer)
{
    extern __shared__ __align__(16) char smc[];
    __nv_bfloat16* wh_s = (__nv_bfloat16*)(smc + WH_OFF);   // init only
    __nv_bfloat16* wl_s = (__nv_bfloat16*)(smc + WL_OFF);   // init only
    __nv_bfloat16* hh_s = (__nv_bfloat16*)(smc + HH_OFF);   // [b][k] pitch HP
    __nv_bfloat16* hl_s = (__nv_bfloat16*)(smc + HL_OFF);
    float* pw   = (float*)(smc + PW_OFF);                   // [kw*16+b][68]
    float* gacc = (float*)(smc + GA_OFF);                   // [b][68]
    const uint32_t smb = smem_u32(smc);
    __shared__ unsigned sE0;
    __shared__ unsigned s_go;                               // release broadcast

    const int tid    = threadIdx.x;
    const int cta    = blockIdx.x;
    const int bgidx  = cta >> 5;            // batch group 0..3
    const int slot   = cta & 31;
    const int b_base = bgidx << 4;
    const int n_base = slot << 4;

    // gate-role indices (tid < 256)
    const int ub = (tid & 255) >> 4;
    const int un = tid & 15;
    const int b_glob = b_base + ub;

    // ---- launch epoch ----
    if (tid == 0) {
        sE0 = *(volatile unsigned*)&g_flag[bgidx][slot];
        s_go = 0u;
    }

    // ---- init: load + split weight tile into smem [jj][k] ----
    for (int e = tid; e < 64 * 512; e += 512) {
        int jj = e >> 9;
        int k  = e & 511;
        int jglob = ((jj >> 4) << 9) + n_base + (jj & 15);
        float v = Whh[(size_t)jglob * HH + k];
        __nv_bfloat16 h = __float2bfloat16_rn(v);
        wh_s[jj * HP + k] = h;
        wl_s[jj * HP + k] = __float2bfloat16_rn(v - __bfloat162float(h));
    }
    // zero OWN slice of initial h buffer
    if (tid < 256) g_hpack[0][b_glob * HH + n_base + un] = 0u;
    __syncthreads();
    const unsigned E0 = sE0;

    // ---- warp role indices ----
    const int wid  = tid >> 5;              // 0..15
    const int lane = tid & 31;
    const int kw   = wid >> 2;               // 0..3: k chunk [kw*128, +128)
    const int jq   = wid & 3;                // 0..3: jj quarter (16 cols)
    const int kbase = kw << 7;
    const int arow = lane & 15;
    const int asel = (lane >> 4) << 3;
    const int brow = (lane & 7) + ((lane >> 4) << 3);
    const int bsel = ((lane >> 3) & 1) << 3;
    const int dr   = lane >> 2;
    const int dq   = lane & 3;

    // ---- load stationary B (weight) fragments: 64 regs/warp ----
    uint32_t Bh[8][4], Bl[8][4];
#pragma unroll
    for (int k16 = 0; k16 < 8; k16++) {
        uint32_t off = (uint32_t)(((jq * 16 + brow) * HP +
                                   kbase + k16 * 16 + bsel) * 2);
        ldsm4(Bh[k16], smb + WH_OFF + off);
        ldsm4(Bl[k16], smb + WL_OFF + off);
    }
    __syncthreads();    // W smem region free; publish initial zeros
    if (tid == 0) {
        __threadfence();
        *(volatile unsigned*)&g_flag[bgidx][slot] = E0 + 1;
    }

    float c_reg = 0.f;

    // staging indices within the 4-warp chunk group (128 threads)
    const int sp = ((wid & 3) << 5) | lane;   // 0..127
    const int sb = sp >> 3;                   // row 0..15
    const int sq = sp & 7;                    // uint4 col phase 0..7

    for (int t = 0; t < TT; t++) {
        // ---- prefetch xg gate pre-activations (overlaps release wait) ----
        float xgi = 0.f, xgf = 0.f, xgg = 0.f, xgo = 0.f;
        if (tid < 256) {
            const float* xr = g_xg + ((size_t)b_glob * TT + t) * G4 + n_base + un;
            xgi = __ldg(xr);
            xgf = __ldg(xr + 512);
            xgg = __ldg(xr + 1024);
            xgo = __ldg(xr + 1536);
        }

        // ---- release: warp 0 polls the 32 flags (ONLY poller), then
        //      broadcasts via smem; other warps spin on LDS ----
        if (wid == 0) {
            const unsigned target = E0 + (unsigned)t + 1u;
            const volatile unsigned* f = &g_flag[bgidx][lane];
            unsigned v;
            do { v = *f; } while (!__all_sync(0xffffffffu, (int)(v - target) >= 0));
            if (lane == 0) *(volatile unsigned*)&s_go = (unsigned)(t + 1);
        } else {
            while (*(volatile unsigned*)&s_go < (unsigned)(t + 1)) { }
        }

        // ---- group-autonomous stage of chunk kw: 16 rows x 128 k ----
        {
            const uint32_t* hrow = g_hpack[t & 1] +
                                   (size_t)(b_base + sb) * HH + kbase;
            __nv_bfloat16* hhrow = hh_s + sb * HP + kbase;
            __nv_bfloat16* hlrow = hl_s + sb * HP + kbase;
#pragma unroll
            for (int j = 0; j < 4; j++) {
                int k4 = sq + (j << 3);           // uint4 index 0..31 in chunk
                uint4 u = ldcg4(hrow + (k4 << 2));
                uint2 hh, hl;
                hh.x = (u.x & 0xFFFFu) | (u.y << 16);
                hh.y = (u.z & 0xFFFFu) | (u.w << 16);
                hl.x = (u.x >> 16) | (u.y & 0xFFFF0000u);
                hl.y = (u.z >> 16) | (u.w & 0xFFFF0000u);
                *(uint2*)(hhrow + (k4 << 2)) = hh;
                *(uint2*)(hlrow + (k4 << 2)) = hl;
            }
            asm volatile("bar.sync %0, 128;" :: "r"(kw + 2) : "memory");
        }

        // ---- MMA: [16b x 128k] x [128k x 16jj], B stationary, parity accs ----
        float acc0[2][4], acc1[2][4];
#pragma unroll
        for (int na = 0; na < 2; na++)
#pragma unroll
            for (int q = 0; q < 4; q++) { acc0[na][q] = 0.f; acc1[na][q] = 0.f; }

#pragma unroll
        for (int k16 = 0; k16 < 8; k16 += 2) {
            uint32_t Ah0[4], Al0[4], Ah1[4], Al1[4];
            uint32_t off0 = (uint32_t)((arow * HP + kbase + k16 * 16 + asel) * 2);
            uint32_t off1 = (uint32_t)((arow * HP + kbase + (k16 + 1) * 16 + asel) * 2);
            ldsm4(Ah0, smb + HH_OFF + off0);
            ldsm4(Al0, smb + HL_OFF + off0);
            ldsm4(Ah1, smb + HH_OFF + off1);
            ldsm4(Al1, smb + HL_OFF + off1);
#pragma unroll
            for (int na = 0; na < 2; na++) {
                mma_bf16(acc0[na], Ah0, &Bh[k16][na * 2]);
                mma_bf16(acc1[na], Ah1, &Bh[k16 + 1][na * 2]);
                mma_bf16(acc0[na], Ah0, &Bl[k16][na * 2]);
                mma_bf16(acc1[na], Ah1, &Bl[k16 + 1][na * 2]);
                mma_bf16(acc0[na], Al0, &Bh[k16][na * 2]);
                mma_bf16(acc1[na], Al1, &Bh[k16 + 1][na * 2]);
            }
        }

        // ---- store per-warp partials: pw[kw*16 + b][jj] (pitch 68) ----
#pragma unroll
        for (int na = 0; na < 2; na++) {
            int col = jq * 16 + na * 8 + dq * 2;
            float2 v0, v1;
            v0.x = acc0[na][0] + acc1[na][0]; v0.y = acc0[na][1] + acc1[na][1];
            v1.x = acc0[na][2] + acc1[na][2]; v1.y = acc0[na][3] + acc1[na][3];
            *(float2*)(pw + ((kw << 4) + dr) * 68 + col)     = v0;
            *(float2*)(pw + ((kw << 4) + dr + 8) * 68 + col) = v1;
        }

        // pw barrier: gate warps block; non-gate warps arrive and run ahead
        if (tid < 256) {
            asm volatile("bar.sync 6, 512;" ::: "memory");
        } else {
            asm volatile("bar.arrive 6, 512;" ::: "memory");
        }

        if (tid < 256) {
            // ---- reduce 4 kw-partials -> gacc[b][jj] ----
            const int rb  = tid >> 4;
            const int rc4 = tid & 15;
            float4 s = *(const float4*)(pw + rb * 68 + (rc4 << 2));
#pragma unroll
            for (int ww = 1; ww < 4; ww++) {
                float4 p = *(const float4*)(pw + ((ww << 4) + rb) * 68 + (rc4 << 2));
                s.x += p.x; s.y += p.y; s.z += p.z; s.w += p.w;
            }
            *(float4*)&gacc[rb * 68 + (rc4 << 2)] = s;
            __syncwarp();   // gacc row produced/consumed within the same warp

            // ---- gate fuse (fast math) + state update + h publish ----
            float gi = gacc[ub * 68 +  0 + un] + xgi;
            float gf = gacc[ub * 68 + 16 + un] + xgf;
            float gg = gacc[ub * 68 + 32 + un] + xgg;
            float go = gacc[ub * 68 + 48 + un] + xgo;

            float si = __fdividef(1.f, 1.f + __expf(-gi));
            float sf = __fdividef(1.f, 1.f + __expf(-gf));
            float so = __fdividef(1.f, 1.f + __expf(-go));
            float tg = __fdividef(2.f, 1.f + __expf(-2.f * gg)) - 1.f;
            float cn = sf * c_reg + si * tg;
            float th = __fdividef(2.f, 1.f + __expf(-2.f * cn)) - 1.f;
            float hn = so * th;
            c_reg = cn;

            __nv_bfloat16 hhi = __float2bfloat16_rn(hn);
            __nv_bfloat16 hlo = __float2bfloat16_rn(hn - __bfloat162float(hhi));
            uint32_t pk = (uint32_t)__bfloat16_as_ushort(hhi) |
                          ((uint32_t)__bfloat16_as_ushort(hlo) << 16);
            g_hpack[(t & 1) ^ 1][b_glob * HH + n_base + un] = pk;

            // gate warps only: h publication stores are complete
            asm volatile("bar.sync 1, 256;" ::: "memory");

            if (t < TT - 1 && tid == 0) {
                __threadfence();
                *(volatile unsigned*)&g_flag[bgidx][slot] = E0 + (unsigned)t + 2u;
            }

            // ---- deferred layer-output store (off the publish path) ----
            size_t oi = ((size_t)b_glob * TT + t) * HH + n_base + un;
            if (final_layer) {
                outf[oi] = hn;
            } else {
                outh[oi] = hhi;
                outl[oi] = hlo;
            }
        }
    }
}

// ============================================================
// Host launcher: 10 graph nodes total.
// ============================================================
extern "C" void kernel_launch(void* const* d_in, const int* in_sizes, int n_in,
                              void* d_out, int out_size)
{
    const float* x    = (const float*)d_in[0];
    const float* w_ih = (const float*)d_in[1];
    const float* w_hh = (const float*)d_in[2];
    const float* b_ih = (const float*)d_in[3];
    const float* b_hh = (const float*)d_in[4];
    float* out = (float*)d_out;

    __nv_bfloat16 *xh, *xl, *wh, *wl;
    cudaGetSymbolAddress((void**)&xh, g_xh);
    cudaGetSymbolAddress((void**)&xl, g_xl);
    cudaGetSymbolAddress((void**)&wh, g_wh);
    cudaGetSymbolAddress((void**)&wl, g_wl);

    static bool attr_set = false;
    if (!attr_set) {
        cudaFuncSetAttribute(rec_persist,
                             cudaFuncAttributeMaxDynamicSharedMemorySize, REC_SMEM);
        cudaFuncSetAttribute(xg_mma2,
                             cudaFuncAttributeMaxDynamicSharedMemorySize, XG2_SMEM);
        attr_set = true;
    }

    dim3 mgrid(16, 512);   // n-tiles x m-tiles
    for (int l = 0; l < 3; l++) {
        const float* Wih = w_ih + (size_t)l * G4 * HH;
        const float* Whh = w_hh + (size_t)l * G4 * HH;
        const int final_layer = (l == 2);

        if (l == 0)
            split_bf16<<<(MTOT * HH) / 256, 256>>>(x, xh, xl);
        // layers 1,2: rec_persist of the previous layer already wrote xh/xl

        split_bf16<<<(G4 * HH) / 256, 256>>>(Wih, wh, wl);
        xg_mma2<<<mgrid, 256, XG2_SMEM>>>(b_ih + l * G4, b_hh + l * G4);
        rec_persist<<<NCTA, 512, REC_SMEM>>>(Whh, out, xh, xl, final_layer);
    }
}

// round 17
// speedup vs baseline: 1.0475x; 1.0475x over previous
#include <cuda_runtime.h>
#include <cuda_bf16.h>
#include <math.h>
#include <stdint.h>

#define BB   64
#define TT   1024
#define HH   512
#define G4   2048        // 4*H
#define MTOT (BB * TT)   // 65536

// ---- static device scratch (no allocation allowed) ----
__device__ float g_xg[(size_t)MTOT * G4];     // 512 MB: per-layer input projection
__device__ uint32_t g_hpack[2][BB * HH];      // ping-pong h as packed (bf16 hi | lo<<16)
__device__ __align__(128) unsigned g_flag[4][32]; // per-(group,slot) publication stamps

// bf16 split operands for the tensor-core input projection
__device__ __nv_bfloat16 g_xh[(size_t)MTOT * HH];  // 64 MB
__device__ __nv_bfloat16 g_xl[(size_t)MTOT * HH];  // 64 MB
__device__ __nv_bfloat16 g_wh[(size_t)G4 * HH];    // 2 MB
__device__ __nv_bfloat16 g_wl[(size_t)G4 * HH];    // 2 MB

// ============================================================
// small PTX helpers (all base-sm_103-safe)
// ============================================================
__device__ __forceinline__ uint32_t smem_u32(const void* p) {
    uint32_t a;
    asm("{ .reg .u64 t; cvta.to.shared.u64 t, %1; cvt.u32.u64 %0, t; }"
        : "=r"(a) : "l"(p));
    return a;
}
__device__ __forceinline__ void ldsm4(uint32_t* r, uint32_t addr) {
    asm volatile("ldmatrix.sync.aligned.m8n8.x4.shared.b16 {%0,%1,%2,%3}, [%4];"
        : "=r"(r[0]), "=r"(r[1]), "=r"(r[2]), "=r"(r[3]) : "r"(addr));
}
__device__ __forceinline__ void mma_bf16(float* d, const uint32_t* a, const uint32_t* b) {
    asm volatile(
        "mma.sync.aligned.m16n8k16.row.col.f32.bf16.bf16.f32 "
        "{%0,%1,%2,%3}, {%4,%5,%6,%7}, {%8,%9}, {%0,%1,%2,%3};"
        : "+f"(d[0]), "+f"(d[1]), "+f"(d[2]), "+f"(d[3])
        : "r"(a[0]), "r"(a[1]), "r"(a[2]), "r"(a[3]), "r"(b[0]), "r"(b[1]));
}
__device__ __forceinline__ void cpa16(uint32_t smaddr, const void* g) {
    asm volatile("cp.async.cg.shared.global [%0], [%1], 16;" :: "r"(smaddr), "l"(g));
}
#define CPA_COMMIT() asm volatile("cp.async.commit_group;" ::: "memory")
#define CPA_WAIT0()  asm volatile("cp.async.wait_group 0;" ::: "memory")

// L2-only vector load (never L1-stale for cross-SM data)
__device__ __forceinline__ uint4 ldcg4(const void* p) {
    uint4 v;
    asm volatile("ld.global.cg.v4.u32 {%0,%1,%2,%3}, [%4];"
        : "=r"(v.x), "=r"(v.y), "=r"(v.z), "=r"(v.w) : "l"(p));
    return v;
}
// release store for flag publish (validated pattern from R8)
__device__ __forceinline__ void strel(unsigned* p, unsigned v) {
    asm volatile("st.release.gpu.global.u32 [%0], %1;" :: "l"(p), "r"(v) : "memory");
}

// ============================================================
// fp32 -> bf16 hi/lo split
// ============================================================
__global__ __launch_bounds__(256) void split_bf16(const float* __restrict__ in,
                                                  __nv_bfloat16* __restrict__ hi,
                                                  __nv_bfloat16* __restrict__ lo)
{
    int i = blockIdx.x * 256 + threadIdx.x;
    float v = in[i];
    __nv_bfloat16 h = __float2bfloat16_rn(v);
    hi[i] = h;
    lo[i] = __float2bfloat16_rn(v - __bfloat162float(h));
}

// ============================================================
// Input projection via mma.sync bf16 (3-pass hi/lo split)  [unchanged]
// ============================================================
#define AP       40
#define ARR_BF16 (128 * AP)
#define XG2_BIAS (8 * ARR_BF16 * 2)
#define XG2_SMEM (XG2_BIAS + 512 + 16)

__global__ __launch_bounds__(256) void xg_mma2(const float* __restrict__ bih,
                                               const float* __restrict__ bhh)
{
    extern __shared__ __align__(16) char sm2[];
    float* bias_sm = (float*)(sm2 + XG2_BIAS);
    const uint32_t smb = smem_u32(sm2);

    const int tid  = threadIdx.x;
    const int wid  = tid >> 5;
    const int lane = tid & 31;
    const int n_blk = blockIdx.x * 128;
    const int m_blk = blockIdx.y * 128;
    const int wm = wid & 1;
    const int wn = wid >> 1;

    if (tid < 128)
        bias_sm[tid] = __ldg(bih + n_blk + tid) + __ldg(bhh + n_blk + tid);

    const __nv_bfloat16* src[4] = {
        g_xh + (size_t)m_blk * HH, g_xl + (size_t)m_blk * HH,
        g_wh + (size_t)n_blk * HH, g_wl + (size_t)n_blk * HH };

    auto load_chunk = [&](int buf, int kc) {
#pragma unroll
        for (int a = 0; a < 4; a++) {
#pragma unroll
            for (int r = 0; r < 2; r++) {
                int unit = tid + r * 256;
                int row  = unit >> 2;
                int u    = unit & 3;
                uint32_t dst = smb +
                    (uint32_t)(((buf * 4 + a) * ARR_BF16 + row * AP + u * 8) * 2);
                cpa16(dst, src[a] + (size_t)row * HH + kc * 32 + u * 8);
            }
        }
    };

    float acc[4][4][4];
#pragma unroll
    for (int i = 0; i < 4; i++)
#pragma unroll
        for (int j = 0; j < 4; j++)
#pragma unroll
            for (int q = 0; q < 4; q++) acc[i][j][q] = 0.f;

    load_chunk(0, 0);
    CPA_COMMIT();

    const int arow  = lane & 15;
    const int asel  = (lane >> 4) << 3;
    const int brow  = (lane & 7) + ((lane >> 4) << 3);
    const int bsel  = ((lane >> 3) & 1) << 3;

    for (int c = 0; c < 16; c++) {
        CPA_WAIT0();
        __syncthreads();
        if (c < 15) { load_chunk((c + 1) & 1, c + 1); CPA_COMMIT(); }

        const uint32_t bufb = smb + (uint32_t)((c & 1) * 4 * ARR_BF16 * 2);
        const uint32_t ah = bufb;
        const uint32_t al = bufb + ARR_BF16 * 2;
        const uint32_t bh = bufb + 2 * ARR_BF16 * 2;
        const uint32_t bl = bufb + 3 * ARR_BF16 * 2;

#pragma unroll
        for (int k16 = 0; k16 < 2; k16++) {
            const int ka = k16 * 16 + asel;
            const int kb = k16 * 16 + bsel;
            uint32_t fah[4][4], fal[4][4], fbh[2][4], fbl[2][4];
#pragma unroll
            for (int ma = 0; ma < 4; ma++) {
                uint32_t off = (uint32_t)(((wm * 64 + ma * 16 + arow) * AP + ka) * 2);
                ldsm4(fah[ma], ah + off);
                ldsm4(fal[ma], al + off);
            }
#pragma unroll
            for (int nb = 0; nb < 2; nb++) {
                uint32_t off = (uint32_t)(((wn * 32 + nb * 16 + brow) * AP + kb) * 2);
                ldsm4(fbh[nb], bh + off);
                ldsm4(fbl[nb], bl + off);
            }
#pragma unroll
            for (int ma = 0; ma < 4; ma++) {
#pragma unroll
                for (int n = 0; n < 4; n++) {
                    const uint32_t* bhf = &fbh[n >> 1][(n & 1) * 2];
                    const uint32_t* blf = &fbl[n >> 1][(n & 1) * 2];
                    mma_bf16(acc[ma][n], fah[ma], bhf);
                    mma_bf16(acc[ma][n], fah[ma], blf);
                    mma_bf16(acc[ma][n], fal[ma], bhf);
                }
            }
        }
    }
    __syncthreads();

    const int r = lane >> 2;
    const int q = lane & 3;
#pragma unroll
    for (int ma = 0; ma < 4; ma++) {
#pragma unroll
        for (int n = 0; n < 4; n++) {
            int m   = m_blk + wm * 64 + ma * 16 + r;
            int col = wn * 32 + n * 8 + q * 2;
            float b0 = bias_sm[col], b1 = bias_sm[col + 1];
            float2 v0, v1;
            v0.x = acc[ma][n][0] + b0; v0.y = acc[ma][n][1] + b1;
            v1.x = acc[ma][n][2] + b0; v1.y = acc[ma][n][3] + b1;
            *(float2*)(g_xg + (size_t)m * G4 + n_blk + col)       = v0;
            *(float2*)(g_xg + (size_t)(m + 8) * G4 + n_blk + col) = v1;
        }
    }
}

// ============================================================
// Persistent recurrence kernel — exact R15 (13.78ms) structure with
// ONE substitution: flag publish uses st.release.gpu (validated in R8)
// instead of __threadfence + volatile store (removes the L1D-flush-
// class fence from the serial publish chain).
// PROTECTED: 512 threads, warp-0-only flag polling, __syncthreads
// release (no smem spin), group staging + named barriers, fast gates,
// fused bf16 layer output.
// ============================================================
#define NCTA 128
#define HP   520                         // bf16 pitch

// steady-state smem (aliases the init-only W staging region)
#define HH_OFF   0                       // 16*520*2 = 16640
#define HL_OFF   16640                   // 16640
#define PW_OFF   33280                   // 4*16*68*4 = 17408
#define GA_OFF   50688                   // 16*68*4  = 4352
// init-only W staging
#define WH_OFF   0                       // 64*520*2 = 66560
#define WL_OFF   66560
#define REC_SMEM 133120

__global__ __launch_bounds__(512, 1) void rec_persist(const float* __restrict__ Whh,
                                                      float* __restrict__ outf,
                                                      __nv_bfloat16* __restrict__ outh,
                                                      __nv_bfloat16* __restrict__ outl,
                                                      int final_layer)
{
    extern __shared__ __align__(16) char smc[];
    __nv_bfloat16* wh_s = (__nv_bfloat16*)(smc + WH_OFF);   // init only
    __nv_bfloat16* wl_s = (__nv_bfloat16*)(smc + WL_OFF);   // init only
    __nv_bfloat16* hh_s = (__nv_bfloat16*)(smc + HH_OFF);   // [b][k] pitch HP
    __nv_bfloat16* hl_s = (__nv_bfloat16*)(smc + HL_OFF);
    float* pw   = (float*)(smc + PW_OFF);                   // [kw*16+b][68]
    float* gacc = (float*)(smc + GA_OFF);                   // [b][68]
    const uint32_t smb = smem_u32(smc);
    __shared__ unsigned sE0;

    const int tid    = threadIdx.x;
    const int cta    = blockIdx.x;
    const int bgidx  = cta >> 5;            // batch group 0..3
    const int slot   = cta & 31;
    const int b_base = bgidx << 4;
    const int n_base = slot << 4;

    // gate-role indices (tid < 256)
    const int ub = (tid & 255) >> 4;
    const int un = tid & 15;
    const int b_glob = b_base + ub;

    // ---- launch epoch ----
    if (tid == 0) sE0 = *(volatile unsigned*)&g_flag[bgidx][slot];

    // ---- init: load + split weight tile into smem [jj][k] ----
    for (int e = tid; e < 64 * 512; e += 512) {
        int jj = e >> 9;
        int k  = e & 511;
        int jglob = ((jj >> 4) << 9) + n_base + (jj & 15);
        float v = Whh[(size_t)jglob * HH + k];
        __nv_bfloat16 h = __float2bfloat16_rn(v);
        wh_s[jj * HP + k] = h;
        wl_s[jj * HP + k] = __float2bfloat16_rn(v - __bfloat162float(h));
    }
    // zero OWN slice of initial h buffer
    if (tid < 256) g_hpack[0][b_glob * HH + n_base + un] = 0u;
    __syncthreads();
    const unsigned E0 = sE0;

    // ---- warp role indices ----
    const int wid  = tid >> 5;              // 0..15
    const int lane = tid & 31;
    const int kw   = wid >> 2;               // 0..3: k chunk [kw*128, +128)
    const int jq   = wid & 3;                // 0..3: jj quarter (16 cols)
    const int kbase = kw << 7;
    const int arow = lane & 15;
    const int asel = (lane >> 4) << 3;
    const int brow = (lane & 7) + ((lane >> 4) << 3);
    const int bsel = ((lane >> 3) & 1) << 3;
    const int dr   = lane >> 2;
    const int dq   = lane & 3;

    // ---- load stationary B (weight) fragments: 64 regs/warp ----
    uint32_t Bh[8][4], Bl[8][4];
#pragma unroll
    for (int k16 = 0; k16 < 8; k16++) {
        uint32_t off = (uint32_t)(((jq * 16 + brow) * HP +
                                   kbase + k16 * 16 + bsel) * 2);
        ldsm4(Bh[k16], smb + WH_OFF + off);
        ldsm4(Bl[k16], smb + WL_OFF + off);
    }
    __syncthreads();    // W smem region free; publish initial zeros
    if (tid == 0) strel(&g_flag[bgidx][slot], E0 + 1);

    float c_reg = 0.f;

    // staging indices within the 4-warp chunk group (128 threads)
    const int sp = ((wid & 3) << 5) | lane;   // 0..127
    const int sb = sp >> 3;                   // row 0..15
    const int sq = sp & 7;                    // uint4 col phase 0..7

    for (int t = 0; t < TT; t++) {
        // ---- prefetch xg gate pre-activations (overlaps poll) ----
        float xgi = 0.f, xgf = 0.f, xgg = 0.f, xgo = 0.f;
        if (tid < 256) {
            const float* xr = g_xg + ((size_t)b_glob * TT + t) * G4 + n_base + un;
            xgi = __ldg(xr);
            xgf = __ldg(xr + 512);
            xgg = __ldg(xr + 1024);
            xgo = __ldg(xr + 1536);
        }

        // ---- wait for all 32 publications of h(t) (WARP 0 ONLY) ----
        if (wid == 0) {
            const unsigned target = E0 + (unsigned)t + 1u;
            const volatile unsigned* f = &g_flag[bgidx][lane];
            unsigned v;
            do { v = *f; } while (!__all_sync(0xffffffffu, (int)(v - target) >= 0));
        }
        __syncthreads();                          // release

        // ---- group-autonomous stage of chunk kw: 16 rows x 128 k ----
        {
            const uint32_t* hrow = g_hpack[t & 1] +
                                   (size_t)(b_base + sb) * HH + kbase;
            __nv_bfloat16* hhrow = hh_s + sb * HP + kbase;
            __nv_bfloat16* hlrow = hl_s + sb * HP + kbase;
#pragma unroll
            for (int j = 0; j < 4; j++) {
                int k4 = sq + (j << 3);           // uint4 index 0..31 in chunk
                uint4 u = ldcg4(hrow + (k4 << 2));
                uint2 hh, hl;
                hh.x = (u.x & 0xFFFFu) | (u.y << 16);
                hh.y = (u.z & 0xFFFFu) | (u.w << 16);
                hl.x = (u.x >> 16) | (u.y & 0xFFFF0000u);
                hl.y = (u.z >> 16) | (u.w & 0xFFFF0000u);
                *(uint2*)(hhrow + (k4 << 2)) = hh;
                *(uint2*)(hlrow + (k4 << 2)) = hl;
            }
            asm volatile("bar.sync %0, 128;" :: "r"(kw + 2) : "memory");
        }

        // ---- MMA: [16b x 128k] x [128k x 16jj], B stationary, parity accs ----
        float acc0[2][4], acc1[2][4];
#pragma unroll
        for (int na = 0; na < 2; na++)
#pragma unroll
            for (int q = 0; q < 4; q++) { acc0[na][q] = 0.f; acc1[na][q] = 0.f; }

#pragma unroll
        for (int k16 = 0; k16 < 8; k16 += 2) {
            uint32_t Ah0[4], Al0[4], Ah1[4], Al1[4];
            uint32_t off0 = (uint32_t)((arow * HP + kbase + k16 * 16 + asel) * 2);
            uint32_t off1 = (uint32_t)((arow * HP + kbase + (k16 + 1) * 16 + asel) * 2);
            ldsm4(Ah0, smb + HH_OFF + off0);
            ldsm4(Al0, smb + HL_OFF + off0);
            ldsm4(Ah1, smb + HH_OFF + off1);
            ldsm4(Al1, smb + HL_OFF + off1);
#pragma unroll
            for (int na = 0; na < 2; na++) {
                mma_bf16(acc0[na], Ah0, &Bh[k16][na * 2]);
                mma_bf16(acc1[na], Ah1, &Bh[k16 + 1][na * 2]);
                mma_bf16(acc0[na], Ah0, &Bl[k16][na * 2]);
                mma_bf16(acc1[na], Ah1, &Bl[k16 + 1][na * 2]);
                mma_bf16(acc0[na], Al0, &Bh[k16][na * 2]);
                mma_bf16(acc1[na], Al1, &Bh[k16 + 1][na * 2]);
            }
        }

        // ---- store per-warp partials: pw[kw*16 + b][jj] (pitch 68) ----
#pragma unroll
        for (int na = 0; na < 2; na++) {
            int col = jq * 16 + na * 8 + dq * 2;
            float2 v0, v1;
            v0.x = acc0[na][0] + acc1[na][0]; v0.y = acc0[na][1] + acc1[na][1];
            v1.x = acc0[na][2] + acc1[na][2]; v1.y = acc0[na][3] + acc1[na][3];
            *(float2*)(pw + ((kw << 4) + dr) * 68 + col)     = v0;
            *(float2*)(pw + ((kw << 4) + dr + 8) * 68 + col) = v1;
        }
        __syncthreads();                          // pw ready

        // ---- reduce 4 kw-partials -> gacc[b][jj] (gate threads) ----
        if (tid < 256) {
            const int rb  = tid >> 4;
            const int rc4 = tid & 15;
            float4 s = *(const float4*)(pw + rb * 68 + (rc4 << 2));
#pragma unroll
            for (int ww = 1; ww < 4; ww++) {
                float4 p = *(const float4*)(pw + ((ww << 4) + rb) * 68 + (rc4 << 2));
                s.x += p.x; s.y += p.y; s.z += p.z; s.w += p.w;
            }
            *(float4*)&gacc[rb * 68 + (rc4 << 2)] = s;
        }
        __syncwarp();   // gacc row produced/consumed within the same warp

        // ---- gate fuse (fast math) + state update + h publish ----
        float hn = 0.f;
        __nv_bfloat16 hhi, hlo;
        if (tid < 256) {
            float gi = gacc[ub * 68 +  0 + un] + xgi;
            float gf = gacc[ub * 68 + 16 + un] + xgf;
            float gg = gacc[ub * 68 + 32 + un] + xgg;
            float go = gacc[ub * 68 + 48 + un] + xgo;

            float si = __fdividef(1.f, 1.f + __expf(-gi));
            float sf = __fdividef(1.f, 1.f + __expf(-gf));
            float so = __fdividef(1.f, 1.f + __expf(-go));
            float tg = __fdividef(2.f, 1.f + __expf(-2.f * gg)) - 1.f;
            float cn = sf * c_reg + si * tg;
            float th = __fdividef(2.f, 1.f + __expf(-2.f * cn)) - 1.f;
            hn = so * th;
            c_reg = cn;

            hhi = __float2bfloat16_rn(hn);
            hlo = __float2bfloat16_rn(hn - __bfloat162float(hhi));
            uint32_t pk = (uint32_t)__bfloat16_as_ushort(hhi) |
                          ((uint32_t)__bfloat16_as_ushort(hlo) << 16);
            g_hpack[(t & 1) ^ 1][b_glob * HH + n_base + un] = pk;

            // gate warps only: h publication stores are complete
            asm volatile("bar.sync 1, 256;" ::: "memory");
        }

        if (t < TT - 1 && tid == 0)
            strel(&g_flag[bgidx][slot], E0 + (unsigned)t + 2u);

        // ---- deferred layer-output store (off the publish critical path) ----
        if (tid < 256) {
            size_t oi = ((size_t)b_glob * TT + t) * HH + n_base + un;
            if (final_layer) {
                outf[oi] = hn;
            } else {
                outh[oi] = hhi;
                outl[oi] = hlo;
            }
        }
    }
}

// ============================================================
// Host launcher: 10 graph nodes total.
// ============================================================
extern "C" void kernel_launch(void* const* d_in, const int* in_sizes, int n_in,
                              void* d_out, int out_size)
{
    const float* x    = (const float*)d_in[0];
    const float* w_ih = (const float*)d_in[1];
    const float* w_hh = (const float*)d_in[2];
    const float* b_ih = (const float*)d_in[3];
    const float* b_hh = (const float*)d_in[4];
    float* out = (float*)d_out;

    __nv_bfloat16 *xh, *xl, *wh, *wl;
    cudaGetSymbolAddress((void**)&xh, g_xh);
    cudaGetSymbolAddress((void**)&xl, g_xl);
    cudaGetSymbolAddress((void**)&wh, g_wh);
    cudaGetSymbolAddress((void**)&wl, g_wl);

    static bool attr_set = false;
    if (!attr_set) {
        cudaFuncSetAttribute(rec_persist,
                             cudaFuncAttributeMaxDynamicSharedMemorySize, REC_SMEM);
        cudaFuncSetAttribute(xg_mma2,
                             cudaFuncAttributeMaxDynamicSharedMemorySize, XG2_SMEM);
        attr_set = true;
    }

    dim3 mgrid(16, 512);   // n-tiles x m-tiles
    for (int l = 0; l < 3; l++) {
        const float* Wih = w_ih + (size_t)l * G4 * HH;
        const float* Whh = w_hh + (size_t)l * G4 * HH;
        const int final_layer = (l == 2);

        if (l == 0)
            split_bf16<<<(MTOT * HH) / 256, 256>>>(x, xh, xl);
        // layers 1,2: rec_persist of the previous layer already wrote xh/xl

        split_bf16<<<(G4 * HH) / 256, 256>>>(Wih, wh, wl);
        xg_mma2<<<mgrid, 256, XG2_SMEM>>>(b_ih + l * G4, b_hh + l * G4);
        rec_persist<<<NCTA, 512, REC_SMEM>>>(Whh, out, xh, xl, final_layer);
    }
}